// round 11
// baseline (speedup 1.0000x reference)
#include <cuda_runtime.h>
#include <cuda_fp16.h>
#include <math.h>
#include <stdint.h>

#define D 128
#define NS_MAX 100000
#define NI_MAX 20000
#define E_MAX  600000

// ---------------- device scratch (static, no allocation) ----------------
__device__ unsigned short g_aggI[(size_t)NI_MAX * D];
__device__ unsigned short g_aggS[(size_t)NS_MAX * D];
__device__ unsigned short g_aggP[(size_t)NS_MAX * D];
__device__ unsigned short g_xs16[(size_t)NS_MAX * D];
__device__ unsigned short g_xi16[(size_t)NI_MAX * D];
__device__ unsigned short g_w_lri[2 * D * D];
__device__ unsigned short g_w_rri[2 * D * D];
__device__ unsigned short g_w_lrs[2 * D * D];
__device__ unsigned short g_w_rrs[2 * D * D];
__device__ unsigned short g_w_p[2 * D * D];

__device__ int g_off_resp[NI_MAX + 1];
__device__ int g_edge_resp[E_MAX];
__device__ int g_off_rev[NS_MAX + 1];
__device__ int g_edge_rev[E_MAX];
__device__ int g_off_prec[NS_MAX + 1];
__device__ int g_edge_prec[E_MAX];

__device__ int g_cnt_resp[NI_MAX];
__device__ int g_cnt_rev[NS_MAX];
__device__ int g_cnt_prec[NS_MAX];

__device__ int   g_bsum[1024];
__device__ float g_colstats[256];   // [0:128) sum, [128:256) sumsq
__device__ float g_bn_ac[256];      // [0:128) a,   [128:256) c

__device__ __forceinline__ uint32_t pack_h2(float a, float b) {
    __half2 h = __float22half2_rn(make_float2(a, b));
    return *(uint32_t*)&h;
}

// ---------------- fused conversion: all fp32 inputs -> fp16 shadows -------------
__global__ void k_cvt_all(
    const float4* __restrict__ xs, const float4* __restrict__ xi,
    const float4* __restrict__ w0, const float4* __restrict__ w1,
    const float4* __restrict__ w2, const float4* __restrict__ w3,
    const float4* __restrict__ w4,
    uint2* __restrict__ oxs, uint2* __restrict__ oxi,
    uint2* __restrict__ ow0, uint2* __restrict__ ow1,
    uint2* __restrict__ ow2, uint2* __restrict__ ow3,
    uint2* __restrict__ ow4,
    int n4s, int n4i, int n4w) {
    int i = blockIdx.x * blockDim.x + threadIdx.x;
    const float4* in; uint2* out; int j;
    if (i < n4s) { in = xs; out = oxs; j = i; }
    else {
        i -= n4s;
        if (i < n4i) { in = xi; out = oxi; j = i; }
        else {
            i -= n4i;
            int ws = i / n4w; j = i - ws * n4w;
            if (ws >= 5) return;
            switch (ws) {
                case 0: in = w0; out = ow0; break;
                case 1: in = w1; out = ow1; break;
                case 2: in = w2; out = ow2; break;
                case 3: in = w3; out = ow3; break;
                default: in = w4; out = ow4; break;
            }
        }
    }
    float4 v = in[j];
    uint2 u; u.x = pack_h2(v.x, v.y); u.y = pack_h2(v.z, v.w);
    out[j] = u;
}

// ---------------- fused CSR build (3 graphs) ----------------
__global__ void k_zero3(int* __restrict__ c1, int n1, int* __restrict__ c2, int n2,
                        int* __restrict__ c3, int n3) {
    int i = blockIdx.x * blockDim.x + threadIdx.x;
    if (i < n1) c1[i] = 0;
    else { i -= n1; if (i < n2) c2[i] = 0;
           else { i -= n2; if (i < n3) c3[i] = 0; } }
}
__global__ void k_count3(const int* __restrict__ d1, int E1, int* __restrict__ c1,
                         const int* __restrict__ d2, int E2, int* __restrict__ c2,
                         const int* __restrict__ d3, int E3, int* __restrict__ c3) {
    int i = blockIdx.x * blockDim.x + threadIdx.x;
    if (i < E1) atomicAdd(&c1[d1[i]], 1);
    else { i -= E1; if (i < E2) atomicAdd(&c2[d2[i]], 1);
           else { i -= E2; if (i < E3) atomicAdd(&c3[d3[i]], 1); } }
}
__global__ void k_scan_block3(
    const int* __restrict__ c1, int n1, int* __restrict__ o1, int nb1,
    const int* __restrict__ c2, int n2, int* __restrict__ o2, int nb2,
    const int* __restrict__ c3, int n3, int* __restrict__ o3,
    int* __restrict__ bsum) {
    __shared__ int sh[1024];
    int tid = threadIdx.x;
    int b = blockIdx.x;
    const int* cnt; int* off; int n; int lb;
    if (b < nb1)            { cnt = c1; off = o1; n = n1; lb = b; }
    else if (b < nb1 + nb2) { cnt = c2; off = o2; n = n2; lb = b - nb1; }
    else                    { cnt = c3; off = o3; n = n3; lb = b - nb1 - nb2; }
    int i = lb * 1024 + tid;
    int v = (i < n) ? cnt[i] : 0;
    sh[tid] = v;
    __syncthreads();
    for (int d = 1; d < 1024; d <<= 1) {
        int t = 0;
        if (tid >= d) t = sh[tid - d];
        __syncthreads();
        if (tid >= d) sh[tid] += t;
        __syncthreads();
    }
    if (i < n) off[i + 1] = sh[tid];
    if (tid == 1023) bsum[blockIdx.x] = sh[1023];
}
__global__ void k_scan_bsum3(int* __restrict__ bsum, int nb1, int nb2, int nb3) {
    __shared__ int sh[3][128];
    int seg = threadIdx.x >> 7;
    int t = threadIdx.x & 127;
    int base = (seg == 0) ? 0 : ((seg == 1) ? nb1 : nb1 + nb2);
    int nb = (seg == 0) ? nb1 : ((seg == 1) ? nb2 : nb3);
    int v = (t < nb) ? bsum[base + t] : 0;
    sh[seg][t] = v;
    __syncthreads();
    for (int d = 1; d < 128; d <<= 1) {
        int x = 0;
        if (t >= d) x = sh[seg][t - d];
        __syncthreads();
        if (t >= d) sh[seg][t] += x;
        __syncthreads();
    }
    if (t < nb) bsum[base + t] = sh[seg][t] - v;
}
__global__ void k_scan_add3(
    int n1, int* __restrict__ o1, int* __restrict__ c1, int nb1,
    int n2, int* __restrict__ o2, int* __restrict__ c2, int nb2,
    int n3, int* __restrict__ o3, int* __restrict__ c3,
    const int* __restrict__ bsum) {
    int b = blockIdx.x;
    int* off; int* cur; int n; int lb;
    if (b < nb1)            { off = o1; cur = c1; n = n1; lb = b; }
    else if (b < nb1 + nb2) { off = o2; cur = c2; n = n2; lb = b - nb1; }
    else                    { off = o3; cur = c3; n = n3; lb = b - nb1 - nb2; }
    int i = lb * 1024 + threadIdx.x;
    if (i < n) {
        int v = off[i + 1] + bsum[b];
        off[i + 1] = v;
        if (i + 1 < n) cur[i + 1] = v;
    }
    if (i == 0) { off[0] = 0; cur[0] = 0; }
}
__global__ void k_fill3(
    const int* __restrict__ s1, const int* __restrict__ d1, int E1,
    int* __restrict__ c1, int* __restrict__ e1,
    const int* __restrict__ s2, const int* __restrict__ d2, int E2,
    int* __restrict__ c2, int* __restrict__ e2,
    const int* __restrict__ s3, const int* __restrict__ d3, int E3,
    int* __restrict__ c3, int* __restrict__ e3) {
    int i = blockIdx.x * blockDim.x + threadIdx.x;
    if (i < E1) { int p = atomicAdd(&c1[d1[i]], 1); e1[p] = s1[i]; }
    else { i -= E1;
        if (i < E2) { int p = atomicAdd(&c2[d2[i]], 1); e2[p] = s2[i]; }
        else { i -= E2;
            if (i < E3) { int p = atomicAdd(&c3[d3[i]], 1); e3[p] = s3[i]; } } }
}

// ---------------- fused gather: 3 aggregations, unrolled x4 for MLP -------------
__global__ void k_gather3(
    const uint2* __restrict__ xsrcS, const uint2* __restrict__ xsrcI,
    const int* __restrict__ eResp, const int* __restrict__ oResp,
    const int* __restrict__ eRev,  const int* __restrict__ oRev,
    const int* __restrict__ ePrec, const int* __restrict__ oPrec,
    uint2* __restrict__ aggI, uint2* __restrict__ aggS, uint2* __restrict__ aggP,
    int NI, int NS, float* __restrict__ colstats) {
    if (blockIdx.x == 0 && threadIdx.x < 256) colstats[threadIdx.x] = 0.f;
    int w = (blockIdx.x * blockDim.x + threadIdx.x) >> 5;
    int lane = threadIdx.x & 31;
    const uint2* x; const int* edges; const int* off; uint2* out;
    int d, domean;
    if (w < NI)           { d = w;          x = xsrcS; edges = eResp; off = oResp; out = aggI; domean = 1; }
    else if (w < NI + NS) { d = w - NI;     x = xsrcI; edges = eRev;  off = oRev;  out = aggS; domean = 1; }
    else if (w < NI + 2 * NS) { d = w - NI - NS; x = xsrcS; edges = ePrec; off = oPrec; out = aggP; domean = 0; }
    else return;

    int beg = off[d], end = off[d + 1];
    float4 a0 = make_float4(0.f, 0.f, 0.f, 0.f);
    float4 a1 = a0, a2 = a0, a3 = a0;
    int e = beg;
    for (; e + 4 <= end; e += 4) {
        int s0 = __ldg(&edges[e]);
        int s1 = __ldg(&edges[e + 1]);
        int s2 = __ldg(&edges[e + 2]);
        int s3 = __ldg(&edges[e + 3]);
        uint2 u0 = __ldg(&x[(size_t)s0 * 32 + lane]);
        uint2 u1 = __ldg(&x[(size_t)s1 * 32 + lane]);
        uint2 u2 = __ldg(&x[(size_t)s2 * 32 + lane]);
        uint2 u3 = __ldg(&x[(size_t)s3 * 32 + lane]);
        float2 f;
        f = __half22float2(*reinterpret_cast<__half2*>(&u0.x)); a0.x += f.x; a0.y += f.y;
        f = __half22float2(*reinterpret_cast<__half2*>(&u0.y)); a0.z += f.x; a0.w += f.y;
        f = __half22float2(*reinterpret_cast<__half2*>(&u1.x)); a1.x += f.x; a1.y += f.y;
        f = __half22float2(*reinterpret_cast<__half2*>(&u1.y)); a1.z += f.x; a1.w += f.y;
        f = __half22float2(*reinterpret_cast<__half2*>(&u2.x)); a2.x += f.x; a2.y += f.y;
        f = __half22float2(*reinterpret_cast<__half2*>(&u2.y)); a2.z += f.x; a2.w += f.y;
        f = __half22float2(*reinterpret_cast<__half2*>(&u3.x)); a3.x += f.x; a3.y += f.y;
        f = __half22float2(*reinterpret_cast<__half2*>(&u3.y)); a3.z += f.x; a3.w += f.y;
    }
    for (; e < end; e++) {
        int s = __ldg(&edges[e]);
        uint2 u = __ldg(&x[(size_t)s * 32 + lane]);
        float2 f;
        f = __half22float2(*reinterpret_cast<__half2*>(&u.x)); a0.x += f.x; a0.y += f.y;
        f = __half22float2(*reinterpret_cast<__half2*>(&u.y)); a0.z += f.x; a0.w += f.y;
    }
    float4 acc;
    acc.x = (a0.x + a1.x) + (a2.x + a3.x);
    acc.y = (a0.y + a1.y) + (a2.y + a3.y);
    acc.z = (a0.z + a1.z) + (a2.z + a3.z);
    acc.w = (a0.w + a1.w) + (a2.w + a3.w);
    if (domean) {
        int c = end - beg; if (c < 1) c = 1;
        float inv = 1.0f / (float)c;
        acc.x *= inv; acc.y *= inv; acc.z *= inv; acc.w *= inv;
    }
    uint2 o;
    o.x = pack_h2(acc.x, acc.y);
    o.y = pack_h2(acc.z, acc.w);
    out[(size_t)d * 32 + lane] = o;
}

// ---------------- FP16 tensor-core GEMM (C-write optional) ----------------
#define BK   32
#define LDW  20
#define TILEW (128 * LDW)

__device__ __forceinline__ void cp16(uint32_t dst, const void* src, int srcsize) {
    asm volatile("cp.async.cg.shared.global [%0], [%1], 16, %2;"
                 :: "r"(dst), "l"(src), "r"(srcsize));
}

__device__ __forceinline__ void mma_f16(float c[4],
                                        uint32_t a0, uint32_t a1, uint32_t a2, uint32_t a3,
                                        uint32_t b0, uint32_t b1) {
    asm volatile(
        "mma.sync.aligned.m16n8k16.row.col.f32.f16.f16.f32 "
        "{%0,%1,%2,%3}, {%4,%5,%6,%7}, {%8,%9}, {%0,%1,%2,%3};"
        : "+f"(c[0]), "+f"(c[1]), "+f"(c[2]), "+f"(c[3])
        : "r"(a0), "r"(a1), "r"(a2), "r"(a3), "r"(b0), "r"(b1));
}

__global__ __launch_bounds__(256, 2) void k_gemm_tc(
    const unsigned short* __restrict__ A0, const unsigned short* __restrict__ A1,
    const unsigned short* __restrict__ A2,
    const unsigned short* __restrict__ W0, const unsigned short* __restrict__ W1,
    const unsigned short* __restrict__ W2,
    const float* __restrict__ b0, const float* __restrict__ b1,
    float scale, int mode, int NA, int M,
    float* __restrict__ C, unsigned short* __restrict__ Cshadow,
    float* __restrict__ colsum, float* __restrict__ colsq) {

    extern __shared__ uint32_t smemu[];
    uint32_t* sA = smemu;
    uint32_t* sB = smemu + 4 * TILEW;
    __shared__ float ssum[128], ssq[128];

    const int tid  = threadIdx.x;
    const int m0   = blockIdx.x * 128;
    const int warp = tid >> 5;
    const int lane = tid & 31;
    const int wm   = warp >> 1;
    const int wn   = warp & 1;
    const int g    = lane >> 2;
    const int t4   = lane & 3;

    const int c0 = tid * 2;

    const unsigned short* Aarr[3] = {A0, A1, A2};
    const unsigned short* Warr[3] = {W0, W1, W2};

    const uint32_t sA_addr = (uint32_t)__cvta_generic_to_shared(sA);
    const uint32_t sB_addr = (uint32_t)__cvta_generic_to_shared(sB);

    float acc[2][8][4];
#pragma unroll
    for (int i = 0; i < 2; i++)
#pragma unroll
        for (int j = 0; j < 8; j++)
#pragma unroll
            for (int c = 0; c < 4; c++) acc[i][j][c] = 0.f;

    const int KT = NA * (D / BK);

    auto issue = [&](int t, int st) {
        int a  = t >> 2;
        int k0 = (t & 3) * BK;
        const unsigned short* A = Aarr[a];
        const unsigned short* W = Warr[a];
        uint32_t dA = sA_addr + st * (TILEW * 4);
        uint32_t dB = sB_addr + st * (TILEW * 4);
#pragma unroll
        for (int i = 0; i < 2; i++) {
            int c   = c0 + i;
            int row = c >> 2;
            int seg = c & 3;
            uint32_t doff = (uint32_t)(row * LDW + seg * 4) * 4;
            int szA = (m0 + row < M) ? 16 : 0;
            cp16(dA + doff, A + (size_t)(m0 + row) * D + k0 + seg * 8, szA);
            cp16(dB + doff, W + (size_t)row * D + k0 + seg * 8, 16);
        }
        asm volatile("cp.async.commit_group;");
    };

#pragma unroll
    for (int s = 0; s < 3; s++) issue(s, s);

    for (int t = 0; t < KT; t++) {
        asm volatile("cp.async.wait_group 2;");
        __syncthreads();

        if (t + 3 < KT) issue(t + 3, (t + 3) & 3);
        else asm volatile("cp.async.commit_group;");

        const uint32_t* cA = sA + (t & 3) * TILEW;
        const uint32_t* cB = sB + (t & 3) * TILEW;
#pragma unroll
        for (int kk2 = 0; kk2 < 2; kk2++) {
            const int wk = kk2 * 8;
            uint32_t af[2][4];
#pragma unroll
            for (int i = 0; i < 2; i++) {
                int mb = wm * 32 + i * 16;
                af[i][0] = cA[(mb + g)     * LDW + wk + t4];
                af[i][1] = cA[(mb + g + 8) * LDW + wk + t4];
                af[i][2] = cA[(mb + g)     * LDW + wk + t4 + 4];
                af[i][3] = cA[(mb + g + 8) * LDW + wk + t4 + 4];
            }
#pragma unroll
            for (int j = 0; j < 8; j++) {
                int nb = wn * 64 + j * 8;
                uint32_t bf0 = cB[(nb + g) * LDW + wk + t4];
                uint32_t bf1 = cB[(nb + g) * LDW + wk + t4 + 4];
                mma_f16(acc[0][j], af[0][0], af[0][1], af[0][2], af[0][3], bf0, bf1);
                mma_f16(acc[1][j], af[1][0], af[1][1], af[1][2], af[1][3], bf0, bf1);
            }
        }
        __syncthreads();
    }

    if (mode == 1) {
        if (tid < 128) { ssum[tid] = 0.f; ssq[tid] = 0.f; }
        __syncthreads();
    }

    float2 bias[8];
#pragma unroll
    for (int j = 0; j < 8; j++) {
        int col = wn * 64 + j * 8 + t4 * 2;
        bias[j].x = b0[col]     + (b1 ? b1[col]     : 0.f);
        bias[j].y = b0[col + 1] + (b1 ? b1[col + 1] : 0.f);
    }

    float ps[16], pq[16];
#pragma unroll
    for (int j = 0; j < 16; j++) { ps[j] = 0.f; pq[j] = 0.f; }

#pragma unroll
    for (int i = 0; i < 2; i++) {
        int row0 = m0 + wm * 32 + i * 16 + g;
        int row1 = row0 + 8;
#pragma unroll
        for (int j = 0; j < 8; j++) {
            int col = wn * 64 + j * 8 + t4 * 2;
            if (row0 < M) {
                float v0 = scale * (acc[i][j][0] + bias[j].x);
                float v1 = scale * (acc[i][j][1] + bias[j].y);
                if (mode == 1) {
                    v0 = (v0 > 0.f) ? v0 : expm1f(v0);
                    v1 = (v1 > 0.f) ? v1 : expm1f(v1);
                    ps[j * 2] += v0; pq[j * 2] += v0 * v0;
                    ps[j * 2 + 1] += v1; pq[j * 2 + 1] += v1 * v1;
                }
                if (C) *(float2*)(C + (size_t)row0 * D + col) = make_float2(v0, v1);
                if (Cshadow)
                    *(uint32_t*)(Cshadow + (size_t)row0 * D + col) = pack_h2(v0, v1);
            }
            if (row1 < M) {
                float v0 = scale * (acc[i][j][2] + bias[j].x);
                float v1 = scale * (acc[i][j][3] + bias[j].y);
                if (mode == 1) {
                    v0 = (v0 > 0.f) ? v0 : expm1f(v0);
                    v1 = (v1 > 0.f) ? v1 : expm1f(v1);
                    ps[j * 2] += v0; pq[j * 2] += v0 * v0;
                    ps[j * 2 + 1] += v1; pq[j * 2 + 1] += v1 * v1;
                }
                if (C) *(float2*)(C + (size_t)row1 * D + col) = make_float2(v0, v1);
                if (Cshadow)
                    *(uint32_t*)(Cshadow + (size_t)row1 * D + col) = pack_h2(v0, v1);
            }
        }
    }

    if (mode == 1) {
#pragma unroll
        for (int j = 0; j < 8; j++) {
            int col = wn * 64 + j * 8 + t4 * 2;
            atomicAdd(&ssum[col], ps[j * 2]);
            atomicAdd(&ssq[col], pq[j * 2]);
            atomicAdd(&ssum[col + 1], ps[j * 2 + 1]);
            atomicAdd(&ssq[col + 1], pq[j * 2 + 1]);
        }
        __syncthreads();
        if (tid < 128) {
            atomicAdd(&colsum[tid], ssum[tid]);
            atomicAdd(&colsq[tid], ssq[tid]);
        }
    }
}

// ---------------- batchnorm ----------------
__global__ void k_bn_prep(const float* __restrict__ stats, const float* __restrict__ g,
                          const float* __restrict__ b, float invN, float* __restrict__ ac) {
    int t = threadIdx.x;
    float m = stats[t] * invN;
    float var = stats[128 + t] * invN - m * m;
    float r = rsqrtf(var + 1e-5f);
    float a = g[t] * r;
    ac[t] = a;
    ac[128 + t] = b[t] - m * a;
}
__global__ void k_bn_apply(float4* __restrict__ x, int n4, const float* __restrict__ ac,
                           uint2* __restrict__ shadow) {
    __shared__ float sa[128], sc[128];
    if (threadIdx.x < 128) { sa[threadIdx.x] = ac[threadIdx.x]; sc[threadIdx.x] = ac[128 + threadIdx.x]; }
    __syncthreads();
    int stride = gridDim.x * blockDim.x;
    for (int i = blockIdx.x * blockDim.x + threadIdx.x; i < n4; i += stride) {
        float4 v = x[i];
        int c = (i & 31) * 4;
        v.x = v.x * sa[c + 0] + sc[c + 0];
        v.y = v.y * sa[c + 1] + sc[c + 1];
        v.z = v.z * sa[c + 2] + sc[c + 2];
        v.w = v.w * sa[c + 3] + sc[c + 3];
        x[i] = v;
        if (shadow) {
            uint2 u;
            u.x = pack_h2(v.x, v.y);
            u.y = pack_h2(v.z, v.w);
            shadow[i] = u;
        }
    }
}

// ---------------- host side ----------------
static void* sym_addr(const void* sym) {
    void* p = nullptr;
    cudaGetSymbolAddress(&p, sym);
    return p;
}

extern "C" void kernel_launch(void* const* d_in, const int* in_sizes, int n_in,
                              void* d_out, int out_size) {
    const float* x_student = (const float*)d_in[0];
    const float* x_item    = (const float*)d_in[1];
    const float* Wl_ri = (const float*)d_in[2];
    const float* bl_ri = (const float*)d_in[3];
    const float* Wr_ri = (const float*)d_in[4];
    const float* Wl_rs = (const float*)d_in[5];
    const float* bl_rs = (const float*)d_in[6];
    const float* Wr_rs = (const float*)d_in[7];
    const float* W_p   = (const float*)d_in[8];
    const float* b_p   = (const float*)d_in[9];
    const float* bn_g  = (const float*)d_in[10];
    const float* bn_b  = (const float*)d_in[11];
    const int* resp_src = (const int*)d_in[12];
    const int* resp_dst = (const int*)d_in[13];
    const int* rev_src  = (const int*)d_in[14];
    const int* rev_dst  = (const int*)d_in[15];
    const int* prec_src = (const int*)d_in[16];
    const int* prec_dst = (const int*)d_in[17];

    const int NS = in_sizes[0] / D;
    const int NI = in_sizes[1] / D;
    const int E1 = in_sizes[12];
    const int E2 = in_sizes[14];
    const int E3 = in_sizes[16];

    unsigned short* aggI = (unsigned short*)sym_addr(g_aggI);
    unsigned short* aggS = (unsigned short*)sym_addr(g_aggS);
    unsigned short* aggP = (unsigned short*)sym_addr(g_aggP);
    unsigned short* xs16 = (unsigned short*)sym_addr(g_xs16);
    unsigned short* xi16 = (unsigned short*)sym_addr(g_xi16);
    unsigned short* w_lri = (unsigned short*)sym_addr(g_w_lri);
    unsigned short* w_rri = (unsigned short*)sym_addr(g_w_rri);
    unsigned short* w_lrs = (unsigned short*)sym_addr(g_w_lrs);
    unsigned short* w_rrs = (unsigned short*)sym_addr(g_w_rrs);
    unsigned short* w_p   = (unsigned short*)sym_addr(g_w_p);
    int* off_resp  = (int*)sym_addr(g_off_resp);
    int* edge_resp = (int*)sym_addr(g_edge_resp);
    int* off_rev   = (int*)sym_addr(g_off_rev);
    int* edge_rev  = (int*)sym_addr(g_edge_rev);
    int* off_prec  = (int*)sym_addr(g_off_prec);
    int* edge_prec = (int*)sym_addr(g_edge_prec);
    int* cnt_resp  = (int*)sym_addr(g_cnt_resp);
    int* cnt_rev   = (int*)sym_addr(g_cnt_rev);
    int* cnt_prec  = (int*)sym_addr(g_cnt_prec);
    int* bsum      = (int*)sym_addr(g_bsum);
    float* colstats = (float*)sym_addr(g_colstats);
    float* bn_ac    = (float*)sym_addr(g_bn_ac);

    float* xi_out = (float*)d_out;                 // NI x D
    float* xs_out = xi_out + (size_t)NI * D;       // NS x D

    static int init_done = 0;
    static cudaStream_t s2;
    static cudaEvent_t ev_fork, ev_cvt, ev_g, ev_j;
    const int SMEM_DYN = 8 * TILEW * 4;  // 81920 B
    if (!init_done) {
        cudaFuncSetAttribute(k_gemm_tc, cudaFuncAttributeMaxDynamicSharedMemorySize, SMEM_DYN);
        cudaStreamCreateWithFlags(&s2, cudaStreamNonBlocking);
        cudaEventCreateWithFlags(&ev_fork, cudaEventDisableTiming);
        cudaEventCreateWithFlags(&ev_cvt, cudaEventDisableTiming);
        cudaEventCreateWithFlags(&ev_g, cudaEventDisableTiming);
        cudaEventCreateWithFlags(&ev_j, cudaEventDisableTiming);
        init_done = 1;
    }

    // ---- fork: cvt_all on s2, concurrent with CSR build on main ----
    cudaEventRecord(ev_fork, 0);
    cudaStreamWaitEvent(s2, ev_fork, 0);
    {
        int n4s = NS * D / 4, n4i = NI * D / 4, n4w = 2 * D * D / 4;
        int tot = n4s + n4i + 5 * n4w;
        k_cvt_all<<<(tot + 255) / 256, 256, 0, s2>>>(
            (const float4*)x_student, (const float4*)x_item,
            (const float4*)Wl_ri, (const float4*)Wr_ri,
            (const float4*)Wl_rs, (const float4*)Wr_rs, (const float4*)W_p,
            (uint2*)xs16, (uint2*)xi16,
            (uint2*)w_lri, (uint2*)w_rri,
            (uint2*)w_lrs, (uint2*)w_rrs, (uint2*)w_p,
            n4s, n4i, n4w);
    }
    cudaEventRecord(ev_cvt, s2);

    // ---- fused CSR build (main stream) ----
    const int Etot = E1 + E2 + E3;
    const int Ntot = NI + NS + NS;
    const int nb1 = (NI + 1023) / 1024;
    const int nb2 = (NS + 1023) / 1024;
    const int nb3 = (NS + 1023) / 1024;
    k_zero3<<<(Ntot + 255) / 256, 256>>>(cnt_resp, NI, cnt_rev, NS, cnt_prec, NS);
    k_count3<<<(Etot + 255) / 256, 256>>>(resp_dst, E1, cnt_resp,
                                          rev_dst, E2, cnt_rev,
                                          prec_dst, E3, cnt_prec);
    k_scan_block3<<<nb1 + nb2 + nb3, 1024>>>(cnt_resp, NI, off_resp, nb1,
                                             cnt_rev, NS, off_rev, nb2,
                                             cnt_prec, NS, off_prec, bsum);
    k_scan_bsum3<<<1, 384>>>(bsum, nb1, nb2, nb3);
    k_scan_add3<<<nb1 + nb2 + nb3, 1024>>>(NI, off_resp, cnt_resp, nb1,
                                           NS, off_rev, cnt_rev, nb2,
                                           NS, off_prec, cnt_prec, bsum);
    k_fill3<<<(Etot + 255) / 256, 256>>>(resp_src, resp_dst, E1, cnt_resp, edge_resp,
                                         rev_src, rev_dst, E2, cnt_rev, edge_rev,
                                         prec_src, prec_dst, E3, cnt_prec, edge_prec);

    // join cvt before first gather
    cudaStreamWaitEvent(0, ev_cvt, 0);

    const int gwTot = NI + 2 * NS;
    const int gBlocks = (gwTot + 7) / 8;
    const int gbI = (NI + 127) / 128;
    const int gbS = (NS + 127) / 128;

    for (int l = 0; l < 2; l++) {
        const size_t wOff = (size_t)l * D * D;
        const size_t bOff = (size_t)l * D;
        const int last = (l == 1);

        // fused gathers (main stream); block 0 zeroes colstats
        k_gather3<<<gBlocks, 256>>>(
            (const uint2*)xs16, (const uint2*)xi16,
            edge_resp, off_resp, edge_rev, off_rev, edge_prec, off_prec,
            (uint2*)aggI, (uint2*)aggS, (uint2*)aggP,
            NI, NS, colstats);
        cudaEventRecord(ev_g, 0);

        // --- branch A (s2): item path (GEMM + BN) ---
        cudaStreamWaitEvent(s2, ev_g, 0);
        k_gemm_tc<<<gbI, 256, SMEM_DYN, s2>>>(aggI, xi16, nullptr,
                                              w_lri + wOff, w_rri + wOff, nullptr,
                                              bl_ri + bOff, nullptr,
                                              1.0f, 1, 2, NI, xi_out, nullptr,
                                              colstats, colstats + 128);
        k_bn_prep<<<1, 128, 0, s2>>>(colstats, bn_g + bOff, bn_b + bOff,
                                     1.0f / (float)NI, bn_ac);
        k_bn_apply<<<512, 256, 0, s2>>>((float4*)xi_out, NI * 32, bn_ac,
                                        last ? nullptr : (uint2*)xi16);
        cudaEventRecord(ev_j, s2);

        // --- branch B (main): student GEMM ---
        // layer 0: fp32 C is a dead store (layer 1 reads only xs16) -> skip it
        k_gemm_tc<<<gbS, 256, SMEM_DYN>>>(aggS, xs16, aggP,
                                          w_lrs + wOff, w_rrs + wOff, w_p + wOff,
                                          bl_rs + bOff, b_p + bOff,
                                          0.5f, 0, 3, NS,
                                          last ? xs_out : nullptr,
                                          last ? nullptr : xs16,
                                          nullptr, nullptr);

        // join branch A before next layer's gather (and before return)
        cudaStreamWaitEvent(0, ev_j, 0);
    }
}

// round 15
// speedup vs baseline: 1.1211x; 1.1211x over previous
#include <cuda_runtime.h>
#include <cuda_fp16.h>
#include <math.h>
#include <stdint.h>

#define D 128
#define NS_MAX 100000
#define NI_MAX 20000
#define E_MAX  600000

// ---------------- device scratch (static, no allocation) ----------------
__device__ unsigned short g_aggI[(size_t)NI_MAX * D];
__device__ unsigned short g_aggS[(size_t)NS_MAX * D];
__device__ unsigned short g_aggP[(size_t)NS_MAX * D];
__device__ unsigned short g_xs16[(size_t)NS_MAX * D];
__device__ unsigned short g_xi16[(size_t)NI_MAX * D];
__device__ unsigned short g_w_lri[2 * D * D];
__device__ unsigned short g_w_rri[2 * D * D];
__device__ unsigned short g_w_lrs[2 * D * D];
__device__ unsigned short g_w_rrs[2 * D * D];
__device__ unsigned short g_w_p[2 * D * D];

__device__ int g_off_resp[NI_MAX + 1];
__device__ int g_edge_resp[E_MAX];
__device__ int g_off_rev[NS_MAX + 1];
__device__ int g_edge_rev[E_MAX];
__device__ int g_off_prec[NS_MAX + 1];
__device__ int g_edge_prec[E_MAX];

__device__ int g_cnt_resp[NI_MAX];
__device__ int g_cnt_rev[NS_MAX];
__device__ int g_cnt_prec[NS_MAX];

__device__ int   g_bsum[1024];
__device__ float g_colstats[256];   // [0:128) sum, [128:256) sumsq
__device__ float g_bn_ac[256];      // [0:128) a,   [128:256) c

__device__ __forceinline__ uint32_t pack_h2(float a, float b) {
    __half2 h = __float22half2_rn(make_float2(a, b));
    return *(uint32_t*)&h;
}

// ---------------- fused conversion: all fp32 inputs -> fp16 shadows -------------
__global__ void k_cvt_all(
    const float4* __restrict__ xs, const float4* __restrict__ xi,
    const float4* __restrict__ w0, const float4* __restrict__ w1,
    const float4* __restrict__ w2, const float4* __restrict__ w3,
    const float4* __restrict__ w4,
    uint2* __restrict__ oxs, uint2* __restrict__ oxi,
    uint2* __restrict__ ow0, uint2* __restrict__ ow1,
    uint2* __restrict__ ow2, uint2* __restrict__ ow3,
    uint2* __restrict__ ow4,
    int n4s, int n4i, int n4w) {
    int i = blockIdx.x * blockDim.x + threadIdx.x;
    const float4* in; uint2* out; int j;
    if (i < n4s) { in = xs; out = oxs; j = i; }
    else {
        i -= n4s;
        if (i < n4i) { in = xi; out = oxi; j = i; }
        else {
            i -= n4i;
            int ws = i / n4w; j = i - ws * n4w;
            if (ws >= 5) return;
            switch (ws) {
                case 0: in = w0; out = ow0; break;
                case 1: in = w1; out = ow1; break;
                case 2: in = w2; out = ow2; break;
                case 3: in = w3; out = ow3; break;
                default: in = w4; out = ow4; break;
            }
        }
    }
    float4 v = in[j];
    uint2 u; u.x = pack_h2(v.x, v.y); u.y = pack_h2(v.z, v.w);
    out[j] = u;
}

// ---------------- fused CSR build (3 graphs) ----------------
__global__ void k_zero3(int* __restrict__ c1, int n1, int* __restrict__ c2, int n2,
                        int* __restrict__ c3, int n3) {
    int i = blockIdx.x * blockDim.x + threadIdx.x;
    if (i < n1) c1[i] = 0;
    else { i -= n1; if (i < n2) c2[i] = 0;
           else { i -= n2; if (i < n3) c3[i] = 0; } }
}
__global__ void k_count3(const int* __restrict__ d1, int E1, int* __restrict__ c1,
                         const int* __restrict__ d2, int E2, int* __restrict__ c2,
                         const int* __restrict__ d3, int E3, int* __restrict__ c3) {
    int i = blockIdx.x * blockDim.x + threadIdx.x;
    if (i < E1) atomicAdd(&c1[d1[i]], 1);
    else { i -= E1; if (i < E2) atomicAdd(&c2[d2[i]], 1);
           else { i -= E2; if (i < E3) atomicAdd(&c3[d3[i]], 1); } }
}
__global__ void k_scan_block3(
    const int* __restrict__ c1, int n1, int* __restrict__ o1, int nb1,
    const int* __restrict__ c2, int n2, int* __restrict__ o2, int nb2,
    const int* __restrict__ c3, int n3, int* __restrict__ o3,
    int* __restrict__ bsum) {
    __shared__ int sh[1024];
    int tid = threadIdx.x;
    int b = blockIdx.x;
    const int* cnt; int* off; int n; int lb;
    if (b < nb1)            { cnt = c1; off = o1; n = n1; lb = b; }
    else if (b < nb1 + nb2) { cnt = c2; off = o2; n = n2; lb = b - nb1; }
    else                    { cnt = c3; off = o3; n = n3; lb = b - nb1 - nb2; }
    int i = lb * 1024 + tid;
    int v = (i < n) ? cnt[i] : 0;
    sh[tid] = v;
    __syncthreads();
    for (int d = 1; d < 1024; d <<= 1) {
        int t = 0;
        if (tid >= d) t = sh[tid - d];
        __syncthreads();
        if (tid >= d) sh[tid] += t;
        __syncthreads();
    }
    if (i < n) off[i + 1] = sh[tid];
    if (tid == 1023) bsum[blockIdx.x] = sh[1023];
}
__global__ void k_scan_bsum3(int* __restrict__ bsum, int nb1, int nb2, int nb3) {
    __shared__ int sh[3][128];
    int seg = threadIdx.x >> 7;
    int t = threadIdx.x & 127;
    int base = (seg == 0) ? 0 : ((seg == 1) ? nb1 : nb1 + nb2);
    int nb = (seg == 0) ? nb1 : ((seg == 1) ? nb2 : nb3);
    int v = (t < nb) ? bsum[base + t] : 0;
    sh[seg][t] = v;
    __syncthreads();
    for (int d = 1; d < 128; d <<= 1) {
        int x = 0;
        if (t >= d) x = sh[seg][t - d];
        __syncthreads();
        if (t >= d) sh[seg][t] += x;
        __syncthreads();
    }
    if (t < nb) bsum[base + t] = sh[seg][t] - v;
}
__global__ void k_scan_add3(
    int n1, int* __restrict__ o1, int* __restrict__ c1, int nb1,
    int n2, int* __restrict__ o2, int* __restrict__ c2, int nb2,
    int n3, int* __restrict__ o3, int* __restrict__ c3,
    const int* __restrict__ bsum) {
    int b = blockIdx.x;
    int* off; int* cur; int n; int lb;
    if (b < nb1)            { off = o1; cur = c1; n = n1; lb = b; }
    else if (b < nb1 + nb2) { off = o2; cur = c2; n = n2; lb = b - nb1; }
    else                    { off = o3; cur = c3; n = n3; lb = b - nb1 - nb2; }
    int i = lb * 1024 + threadIdx.x;
    if (i < n) {
        int v = off[i + 1] + bsum[b];
        off[i + 1] = v;
        if (i + 1 < n) cur[i + 1] = v;
    }
    if (i == 0) { off[0] = 0; cur[0] = 0; }
}
__global__ void k_fill3(
    const int* __restrict__ s1, const int* __restrict__ d1, int E1,
    int* __restrict__ c1, int* __restrict__ e1,
    const int* __restrict__ s2, const int* __restrict__ d2, int E2,
    int* __restrict__ c2, int* __restrict__ e2,
    const int* __restrict__ s3, const int* __restrict__ d3, int E3,
    int* __restrict__ c3, int* __restrict__ e3) {
    int i = blockIdx.x * blockDim.x + threadIdx.x;
    if (i < E1) { int p = atomicAdd(&c1[d1[i]], 1); e1[p] = s1[i]; }
    else { i -= E1;
        if (i < E2) { int p = atomicAdd(&c2[d2[i]], 1); e2[p] = s2[i]; }
        else { i -= E2;
            if (i < E3) { int p = atomicAdd(&c3[d3[i]], 1); e3[p] = s3[i]; } } }
}

// ---------------- fused gather (round-10 proven form: single accumulator) -------
__global__ void k_gather3(
    const uint2* __restrict__ xsrcS, const uint2* __restrict__ xsrcI,
    const int* __restrict__ eResp, const int* __restrict__ oResp,
    const int* __restrict__ eRev,  const int* __restrict__ oRev,
    const int* __restrict__ ePrec, const int* __restrict__ oPrec,
    uint2* __restrict__ aggI, uint2* __restrict__ aggS, uint2* __restrict__ aggP,
    int NI, int NS, float* __restrict__ colstats) {
    if (blockIdx.x == 0 && threadIdx.x < 256) colstats[threadIdx.x] = 0.f;
    int w = (blockIdx.x * blockDim.x + threadIdx.x) >> 5;
    int lane = threadIdx.x & 31;
    const uint2* x; const int* edges; const int* off; uint2* out;
    int d, domean;
    if (w < NI)           { d = w;          x = xsrcS; edges = eResp; off = oResp; out = aggI; domean = 1; }
    else if (w < NI + NS) { d = w - NI;     x = xsrcI; edges = eRev;  off = oRev;  out = aggS; domean = 1; }
    else if (w < NI + 2 * NS) { d = w - NI - NS; x = xsrcS; edges = ePrec; off = oPrec; out = aggP; domean = 0; }
    else return;

    int beg = off[d], end = off[d + 1];
    float4 acc = make_float4(0.f, 0.f, 0.f, 0.f);
    for (int e = beg; e < end; e++) {
        int s = edges[e];
        uint2 u = __ldg(&x[(size_t)s * 32 + lane]);
        __half2 h0 = *reinterpret_cast<__half2*>(&u.x);
        __half2 h1 = *reinterpret_cast<__half2*>(&u.y);
        float2 f0 = __half22float2(h0);
        float2 f1 = __half22float2(h1);
        acc.x += f0.x; acc.y += f0.y; acc.z += f1.x; acc.w += f1.y;
    }
    if (domean) {
        int c = end - beg; if (c < 1) c = 1;
        float inv = 1.0f / (float)c;
        acc.x *= inv; acc.y *= inv; acc.z *= inv; acc.w *= inv;
    }
    uint2 o;
    o.x = pack_h2(acc.x, acc.y);
    o.y = pack_h2(acc.z, acc.w);
    out[(size_t)d * 32 + lane] = o;
}

// ---------------- FP16 tensor-core GEMM (C-write optional) ----------------
#define BK   32
#define LDW  20
#define TILEW (128 * LDW)

__device__ __forceinline__ void cp16(uint32_t dst, const void* src, int srcsize) {
    asm volatile("cp.async.cg.shared.global [%0], [%1], 16, %2;"
                 :: "r"(dst), "l"(src), "r"(srcsize));
}

__device__ __forceinline__ void mma_f16(float c[4],
                                        uint32_t a0, uint32_t a1, uint32_t a2, uint32_t a3,
                                        uint32_t b0, uint32_t b1) {
    asm volatile(
        "mma.sync.aligned.m16n8k16.row.col.f32.f16.f16.f32 "
        "{%0,%1,%2,%3}, {%4,%5,%6,%7}, {%8,%9}, {%0,%1,%2,%3};"
        : "+f"(c[0]), "+f"(c[1]), "+f"(c[2]), "+f"(c[3])
        : "r"(a0), "r"(a1), "r"(a2), "r"(a3), "r"(b0), "r"(b1));
}

__global__ __launch_bounds__(256, 2) void k_gemm_tc(
    const unsigned short* __restrict__ A0, const unsigned short* __restrict__ A1,
    const unsigned short* __restrict__ A2,
    const unsigned short* __restrict__ W0, const unsigned short* __restrict__ W1,
    const unsigned short* __restrict__ W2,
    const float* __restrict__ b0, const float* __restrict__ b1,
    float scale, int mode, int NA, int M,
    float* __restrict__ C, unsigned short* __restrict__ Cshadow,
    float* __restrict__ colsum, float* __restrict__ colsq) {

    extern __shared__ uint32_t smemu[];
    uint32_t* sA = smemu;
    uint32_t* sB = smemu + 4 * TILEW;
    __shared__ float ssum[128], ssq[128];

    const int tid  = threadIdx.x;
    const int m0   = blockIdx.x * 128;
    const int warp = tid >> 5;
    const int lane = tid & 31;
    const int wm   = warp >> 1;
    const int wn   = warp & 1;
    const int g    = lane >> 2;
    const int t4   = lane & 3;

    const int c0 = tid * 2;

    const unsigned short* Aarr[3] = {A0, A1, A2};
    const unsigned short* Warr[3] = {W0, W1, W2};

    const uint32_t sA_addr = (uint32_t)__cvta_generic_to_shared(sA);
    const uint32_t sB_addr = (uint32_t)__cvta_generic_to_shared(sB);

    float acc[2][8][4];
#pragma unroll
    for (int i = 0; i < 2; i++)
#pragma unroll
        for (int j = 0; j < 8; j++)
#pragma unroll
            for (int c = 0; c < 4; c++) acc[i][j][c] = 0.f;

    const int KT = NA * (D / BK);

    auto issue = [&](int t, int st) {
        int a  = t >> 2;
        int k0 = (t & 3) * BK;
        const unsigned short* A = Aarr[a];
        const unsigned short* W = Warr[a];
        uint32_t dA = sA_addr + st * (TILEW * 4);
        uint32_t dB = sB_addr + st * (TILEW * 4);
#pragma unroll
        for (int i = 0; i < 2; i++) {
            int c   = c0 + i;
            int row = c >> 2;
            int seg = c & 3;
            uint32_t doff = (uint32_t)(row * LDW + seg * 4) * 4;
            int szA = (m0 + row < M) ? 16 : 0;
            cp16(dA + doff, A + (size_t)(m0 + row) * D + k0 + seg * 8, szA);
            cp16(dB + doff, W + (size_t)row * D + k0 + seg * 8, 16);
        }
        asm volatile("cp.async.commit_group;");
    };

#pragma unroll
    for (int s = 0; s < 3; s++) issue(s, s);

    for (int t = 0; t < KT; t++) {
        asm volatile("cp.async.wait_group 2;");
        __syncthreads();

        if (t + 3 < KT) issue(t + 3, (t + 3) & 3);
        else asm volatile("cp.async.commit_group;");

        const uint32_t* cA = sA + (t & 3) * TILEW;
        const uint32_t* cB = sB + (t & 3) * TILEW;
#pragma unroll
        for (int kk2 = 0; kk2 < 2; kk2++) {
            const int wk = kk2 * 8;
            uint32_t af[2][4];
#pragma unroll
            for (int i = 0; i < 2; i++) {
                int mb = wm * 32 + i * 16;
                af[i][0] = cA[(mb + g)     * LDW + wk + t4];
                af[i][1] = cA[(mb + g + 8) * LDW + wk + t4];
                af[i][2] = cA[(mb + g)     * LDW + wk + t4 + 4];
                af[i][3] = cA[(mb + g + 8) * LDW + wk + t4 + 4];
            }
#pragma unroll
            for (int j = 0; j < 8; j++) {
                int nb = wn * 64 + j * 8;
                uint32_t bf0 = cB[(nb + g) * LDW + wk + t4];
                uint32_t bf1 = cB[(nb + g) * LDW + wk + t4 + 4];
                mma_f16(acc[0][j], af[0][0], af[0][1], af[0][2], af[0][3], bf0, bf1);
                mma_f16(acc[1][j], af[1][0], af[1][1], af[1][2], af[1][3], bf0, bf1);
            }
        }
        __syncthreads();
    }

    if (mode == 1) {
        if (tid < 128) { ssum[tid] = 0.f; ssq[tid] = 0.f; }
        __syncthreads();
    }

    float2 bias[8];
#pragma unroll
    for (int j = 0; j < 8; j++) {
        int col = wn * 64 + j * 8 + t4 * 2;
        bias[j].x = b0[col]     + (b1 ? b1[col]     : 0.f);
        bias[j].y = b0[col + 1] + (b1 ? b1[col + 1] : 0.f);
    }

    float ps[16], pq[16];
#pragma unroll
    for (int j = 0; j < 16; j++) { ps[j] = 0.f; pq[j] = 0.f; }

#pragma unroll
    for (int i = 0; i < 2; i++) {
        int row0 = m0 + wm * 32 + i * 16 + g;
        int row1 = row0 + 8;
#pragma unroll
        for (int j = 0; j < 8; j++) {
            int col = wn * 64 + j * 8 + t4 * 2;
            if (row0 < M) {
                float v0 = scale * (acc[i][j][0] + bias[j].x);
                float v1 = scale * (acc[i][j][1] + bias[j].y);
                if (mode == 1) {
                    v0 = (v0 > 0.f) ? v0 : expm1f(v0);
                    v1 = (v1 > 0.f) ? v1 : expm1f(v1);
                    ps[j * 2] += v0; pq[j * 2] += v0 * v0;
                    ps[j * 2 + 1] += v1; pq[j * 2 + 1] += v1 * v1;
                }
                if (C) *(float2*)(C + (size_t)row0 * D + col) = make_float2(v0, v1);
                if (Cshadow)
                    *(uint32_t*)(Cshadow + (size_t)row0 * D + col) = pack_h2(v0, v1);
            }
            if (row1 < M) {
                float v0 = scale * (acc[i][j][2] + bias[j].x);
                float v1 = scale * (acc[i][j][3] + bias[j].y);
                if (mode == 1) {
                    v0 = (v0 > 0.f) ? v0 : expm1f(v0);
                    v1 = (v1 > 0.f) ? v1 : expm1f(v1);
                    ps[j * 2] += v0; pq[j * 2] += v0 * v0;
                    ps[j * 2 + 1] += v1; pq[j * 2 + 1] += v1 * v1;
                }
                if (C) *(float2*)(C + (size_t)row1 * D + col) = make_float2(v0, v1);
                if (Cshadow)
                    *(uint32_t*)(Cshadow + (size_t)row1 * D + col) = pack_h2(v0, v1);
            }
        }
    }

    if (mode == 1) {
#pragma unroll
        for (int j = 0; j < 8; j++) {
            int col = wn * 64 + j * 8 + t4 * 2;
            atomicAdd(&ssum[col], ps[j * 2]);
            atomicAdd(&ssq[col], pq[j * 2]);
            atomicAdd(&ssum[col + 1], ps[j * 2 + 1]);
            atomicAdd(&ssq[col + 1], pq[j * 2 + 1]);
        }
        __syncthreads();
        if (tid < 128) {
            atomicAdd(&colsum[tid], ssum[tid]);
            atomicAdd(&colsq[tid], ssq[tid]);
        }
    }
}

// ---------------- batchnorm ----------------
__global__ void k_bn_prep(const float* __restrict__ stats, const float* __restrict__ g,
                          const float* __restrict__ b, float invN, float* __restrict__ ac) {
    int t = threadIdx.x;
    float m = stats[t] * invN;
    float var = stats[128 + t] * invN - m * m;
    float r = rsqrtf(var + 1e-5f);
    float a = g[t] * r;
    ac[t] = a;
    ac[128 + t] = b[t] - m * a;
}
__global__ void k_bn_apply(float4* __restrict__ x, int n4, const float* __restrict__ ac,
                           uint2* __restrict__ shadow) {
    __shared__ float sa[128], sc[128];
    if (threadIdx.x < 128) { sa[threadIdx.x] = ac[threadIdx.x]; sc[threadIdx.x] = ac[128 + threadIdx.x]; }
    __syncthreads();
    int stride = gridDim.x * blockDim.x;
    for (int i = blockIdx.x * blockDim.x + threadIdx.x; i < n4; i += stride) {
        float4 v = x[i];
        int c = (i & 31) * 4;
        v.x = v.x * sa[c + 0] + sc[c + 0];
        v.y = v.y * sa[c + 1] + sc[c + 1];
        v.z = v.z * sa[c + 2] + sc[c + 2];
        v.w = v.w * sa[c + 3] + sc[c + 3];
        x[i] = v;
        if (shadow) {
            uint2 u;
            u.x = pack_h2(v.x, v.y);
            u.y = pack_h2(v.z, v.w);
            shadow[i] = u;
        }
    }
}

// ---------------- host side ----------------
static void* sym_addr(const void* sym) {
    void* p = nullptr;
    cudaGetSymbolAddress(&p, sym);
    return p;
}

extern "C" void kernel_launch(void* const* d_in, const int* in_sizes, int n_in,
                              void* d_out, int out_size) {
    const float* x_student = (const float*)d_in[0];
    const float* x_item    = (const float*)d_in[1];
    const float* Wl_ri = (const float*)d_in[2];
    const float* bl_ri = (const float*)d_in[3];
    const float* Wr_ri = (const float*)d_in[4];
    const float* Wl_rs = (const float*)d_in[5];
    const float* bl_rs = (const float*)d_in[6];
    const float* Wr_rs = (const float*)d_in[7];
    const float* W_p   = (const float*)d_in[8];
    const float* b_p   = (const float*)d_in[9];
    const float* bn_g  = (const float*)d_in[10];
    const float* bn_b  = (const float*)d_in[11];
    const int* resp_src = (const int*)d_in[12];
    const int* resp_dst = (const int*)d_in[13];
    const int* rev_src  = (const int*)d_in[14];
    const int* rev_dst  = (const int*)d_in[15];
    const int* prec_src = (const int*)d_in[16];
    const int* prec_dst = (const int*)d_in[17];

    const int NS = in_sizes[0] / D;
    const int NI = in_sizes[1] / D;
    const int E1 = in_sizes[12];
    const int E2 = in_sizes[14];
    const int E3 = in_sizes[16];

    unsigned short* aggI = (unsigned short*)sym_addr(g_aggI);
    unsigned short* aggS = (unsigned short*)sym_addr(g_aggS);
    unsigned short* aggP = (unsigned short*)sym_addr(g_aggP);
    unsigned short* xs16 = (unsigned short*)sym_addr(g_xs16);
    unsigned short* xi16 = (unsigned short*)sym_addr(g_xi16);
    unsigned short* w_lri = (unsigned short*)sym_addr(g_w_lri);
    unsigned short* w_rri = (unsigned short*)sym_addr(g_w_rri);
    unsigned short* w_lrs = (unsigned short*)sym_addr(g_w_lrs);
    unsigned short* w_rrs = (unsigned short*)sym_addr(g_w_rrs);
    unsigned short* w_p   = (unsigned short*)sym_addr(g_w_p);
    int* off_resp  = (int*)sym_addr(g_off_resp);
    int* edge_resp = (int*)sym_addr(g_edge_resp);
    int* off_rev   = (int*)sym_addr(g_off_rev);
    int* edge_rev  = (int*)sym_addr(g_edge_rev);
    int* off_prec  = (int*)sym_addr(g_off_prec);
    int* edge_prec = (int*)sym_addr(g_edge_prec);
    int* cnt_resp  = (int*)sym_addr(g_cnt_resp);
    int* cnt_rev   = (int*)sym_addr(g_cnt_rev);
    int* cnt_prec  = (int*)sym_addr(g_cnt_prec);
    int* bsum      = (int*)sym_addr(g_bsum);
    float* colstats = (float*)sym_addr(g_colstats);
    float* bn_ac    = (float*)sym_addr(g_bn_ac);

    float* xi_out = (float*)d_out;                 // NI x D
    float* xs_out = xi_out + (size_t)NI * D;       // NS x D

    static int init_done = 0;
    static cudaStream_t s2;
    static cudaEvent_t ev_fork, ev_cvt, ev_g, ev_j;
    const int SMEM_DYN = 8 * TILEW * 4;  // 81920 B
    if (!init_done) {
        cudaFuncSetAttribute(k_gemm_tc, cudaFuncAttributeMaxDynamicSharedMemorySize, SMEM_DYN);
        cudaStreamCreateWithFlags(&s2, cudaStreamNonBlocking);
        cudaEventCreateWithFlags(&ev_fork, cudaEventDisableTiming);
        cudaEventCreateWithFlags(&ev_cvt, cudaEventDisableTiming);
        cudaEventCreateWithFlags(&ev_g, cudaEventDisableTiming);
        cudaEventCreateWithFlags(&ev_j, cudaEventDisableTiming);
        init_done = 1;
    }

    // ---- fork: cvt_all on s2, concurrent with CSR build on main ----
    cudaEventRecord(ev_fork, 0);
    cudaStreamWaitEvent(s2, ev_fork, 0);
    {
        int n4s = NS * D / 4, n4i = NI * D / 4, n4w = 2 * D * D / 4;
        int tot = n4s + n4i + 5 * n4w;
        k_cvt_all<<<(tot + 255) / 256, 256, 0, s2>>>(
            (const float4*)x_student, (const float4*)x_item,
            (const float4*)Wl_ri, (const float4*)Wr_ri,
            (const float4*)Wl_rs, (const float4*)Wr_rs, (const float4*)W_p,
            (uint2*)xs16, (uint2*)xi16,
            (uint2*)w_lri, (uint2*)w_rri,
            (uint2*)w_lrs, (uint2*)w_rrs, (uint2*)w_p,
            n4s, n4i, n4w);
    }
    cudaEventRecord(ev_cvt, s2);

    // ---- fused CSR build (main stream) ----
    const int Etot = E1 + E2 + E3;
    const int Ntot = NI + NS + NS;
    const int nb1 = (NI + 1023) / 1024;
    const int nb2 = (NS + 1023) / 1024;
    const int nb3 = (NS + 1023) / 1024;
    k_zero3<<<(Ntot + 255) / 256, 256>>>(cnt_resp, NI, cnt_rev, NS, cnt_prec, NS);
    k_count3<<<(Etot + 255) / 256, 256>>>(resp_dst, E1, cnt_resp,
                                          rev_dst, E2, cnt_rev,
                                          prec_dst, E3, cnt_prec);
    k_scan_block3<<<nb1 + nb2 + nb3, 1024>>>(cnt_resp, NI, off_resp, nb1,
                                             cnt_rev, NS, off_rev, nb2,
                                             cnt_prec, NS, off_prec, bsum);
    k_scan_bsum3<<<1, 384>>>(bsum, nb1, nb2, nb3);
    k_scan_add3<<<nb1 + nb2 + nb3, 1024>>>(NI, off_resp, cnt_resp, nb1,
                                           NS, off_rev, cnt_rev, nb2,
                                           NS, off_prec, cnt_prec, bsum);
    k_fill3<<<(Etot + 255) / 256, 256>>>(resp_src, resp_dst, E1, cnt_resp, edge_resp,
                                         rev_src, rev_dst, E2, cnt_rev, edge_rev,
                                         prec_src, prec_dst, E3, cnt_prec, edge_prec);

    // join cvt before first gather
    cudaStreamWaitEvent(0, ev_cvt, 0);

    const int gwTot = NI + 2 * NS;
    const int gBlocks = (gwTot + 7) / 8;
    const int gbI = (NI + 127) / 128;
    const int gbS = (NS + 127) / 128;

    for (int l = 0; l < 2; l++) {
        const size_t wOff = (size_t)l * D * D;
        const size_t bOff = (size_t)l * D;
        const int last = (l == 1);

        // fused gathers (main stream); block 0 zeroes colstats
        k_gather3<<<gBlocks, 256>>>(
            (const uint2*)xs16, (const uint2*)xi16,
            edge_resp, off_resp, edge_rev, off_rev, edge_prec, off_prec,
            (uint2*)aggI, (uint2*)aggS, (uint2*)aggP,
            NI, NS, colstats);
        cudaEventRecord(ev_g, 0);

        // --- branch A (s2): item path (GEMM + BN) ---
        cudaStreamWaitEvent(s2, ev_g, 0);
        k_gemm_tc<<<gbI, 256, SMEM_DYN, s2>>>(aggI, xi16, nullptr,
                                              w_lri + wOff, w_rri + wOff, nullptr,
                                              bl_ri + bOff, nullptr,
                                              1.0f, 1, 2, NI, xi_out, nullptr,
                                              colstats, colstats + 128);
        k_bn_prep<<<1, 128, 0, s2>>>(colstats, bn_g + bOff, bn_b + bOff,
                                     1.0f / (float)NI, bn_ac);
        k_bn_apply<<<512, 256, 0, s2>>>((float4*)xi_out, NI * 32, bn_ac,
                                        last ? nullptr : (uint2*)xi16);
        cudaEventRecord(ev_j, s2);

        // --- branch B (main): student GEMM ---
        // layer 0: fp32 C is a dead store (layer 1 reads only xs16) -> skip it
        k_gemm_tc<<<gbS, 256, SMEM_DYN>>>(aggS, xs16, aggP,
                                          w_lrs + wOff, w_rrs + wOff, w_p + wOff,
                                          bl_rs + bOff, b_p + bOff,
                                          0.5f, 0, 3, NS,
                                          last ? xs_out : nullptr,
                                          last ? nullptr : xs16,
                                          nullptr, nullptr);

        // join branch A before next layer's gather (and before return)
        cudaStreamWaitEvent(0, ev_j, 0);
    }
}

// round 16
// speedup vs baseline: 1.2001x; 1.0705x over previous
#include <cuda_runtime.h>
#include <cuda_fp16.h>
#include <math.h>
#include <stdint.h>

#define D 128
#define NS_MAX 100000
#define NI_MAX 20000
#define E_MAX  600000

// ---------------- device scratch (static, no allocation) ----------------
__device__ unsigned short g_aggI[(size_t)NI_MAX * D];
__device__ unsigned short g_aggS[(size_t)NS_MAX * D];
__device__ unsigned short g_aggP[(size_t)NS_MAX * D];
__device__ unsigned short g_xs16[(size_t)NS_MAX * D];
__device__ unsigned short g_xi16[(size_t)NI_MAX * D];
__device__ unsigned short g_w_lri[2 * D * D];
__device__ unsigned short g_w_rri[2 * D * D];
__device__ unsigned short g_w_lrs[2 * D * D];
__device__ unsigned short g_w_rrs[2 * D * D];
__device__ unsigned short g_w_p[2 * D * D];

__device__ int g_off_resp[NI_MAX + 1];
__device__ int g_edge_resp[E_MAX];
__device__ int g_off_rev[NS_MAX + 1];
__device__ int g_edge_rev[E_MAX];
__device__ int g_off_prec[NS_MAX + 1];
__device__ int g_edge_prec[E_MAX];

__device__ int g_cnt_resp[NI_MAX];
__device__ int g_cnt_rev[NS_MAX];
__device__ int g_cnt_prec[NS_MAX];

__device__ int   g_bsum[1024];
__device__ float g_colstats[256];   // [0:128) sum, [128:256) sumsq
__device__ float g_bn_ac[256];      // [0:128) a,   [128:256) c

__device__ __forceinline__ uint32_t pack_h2(float a, float b) {
    __half2 h = __float22half2_rn(make_float2(a, b));
    return *(uint32_t*)&h;
}

// ---------------- fused conversion: all fp32 inputs -> fp16 shadows -------------
__global__ void k_cvt_all(
    const float4* __restrict__ xs, const float4* __restrict__ xi,
    const float4* __restrict__ w0, const float4* __restrict__ w1,
    const float4* __restrict__ w2, const float4* __restrict__ w3,
    const float4* __restrict__ w4,
    uint2* __restrict__ oxs, uint2* __restrict__ oxi,
    uint2* __restrict__ ow0, uint2* __restrict__ ow1,
    uint2* __restrict__ ow2, uint2* __restrict__ ow3,
    uint2* __restrict__ ow4,
    int n4s, int n4i, int n4w) {
    int i = blockIdx.x * blockDim.x + threadIdx.x;
    const float4* in; uint2* out; int j;
    if (i < n4s) { in = xs; out = oxs; j = i; }
    else {
        i -= n4s;
        if (i < n4i) { in = xi; out = oxi; j = i; }
        else {
            i -= n4i;
            int ws = i / n4w; j = i - ws * n4w;
            if (ws >= 5) return;
            switch (ws) {
                case 0: in = w0; out = ow0; break;
                case 1: in = w1; out = ow1; break;
                case 2: in = w2; out = ow2; break;
                case 3: in = w3; out = ow3; break;
                default: in = w4; out = ow4; break;
            }
        }
    }
    float4 v = in[j];
    uint2 u; u.x = pack_h2(v.x, v.y); u.y = pack_h2(v.z, v.w);
    out[j] = u;
}

// ---------------- fused CSR build (3 graphs) ----------------
__global__ void k_zero3(int* __restrict__ c1, int n1, int* __restrict__ c2, int n2,
                        int* __restrict__ c3, int n3) {
    int i = blockIdx.x * blockDim.x + threadIdx.x;
    if (i < n1) c1[i] = 0;
    else { i -= n1; if (i < n2) c2[i] = 0;
           else { i -= n2; if (i < n3) c3[i] = 0; } }
}
__global__ void k_count3(const int* __restrict__ d1, int E1, int* __restrict__ c1,
                         const int* __restrict__ d2, int E2, int* __restrict__ c2,
                         const int* __restrict__ d3, int E3, int* __restrict__ c3) {
    int i = blockIdx.x * blockDim.x + threadIdx.x;
    if (i < E1) atomicAdd(&c1[d1[i]], 1);
    else { i -= E1; if (i < E2) atomicAdd(&c2[d2[i]], 1);
           else { i -= E2; if (i < E3) atomicAdd(&c3[d3[i]], 1); } }
}
__global__ void k_scan_block3(
    const int* __restrict__ c1, int n1, int* __restrict__ o1, int nb1,
    const int* __restrict__ c2, int n2, int* __restrict__ o2, int nb2,
    const int* __restrict__ c3, int n3, int* __restrict__ o3,
    int* __restrict__ bsum) {
    __shared__ int sh[1024];
    int tid = threadIdx.x;
    int b = blockIdx.x;
    const int* cnt; int* off; int n; int lb;
    if (b < nb1)            { cnt = c1; off = o1; n = n1; lb = b; }
    else if (b < nb1 + nb2) { cnt = c2; off = o2; n = n2; lb = b - nb1; }
    else                    { cnt = c3; off = o3; n = n3; lb = b - nb1 - nb2; }
    int i = lb * 1024 + tid;
    int v = (i < n) ? cnt[i] : 0;
    sh[tid] = v;
    __syncthreads();
    for (int d = 1; d < 1024; d <<= 1) {
        int t = 0;
        if (tid >= d) t = sh[tid - d];
        __syncthreads();
        if (tid >= d) sh[tid] += t;
        __syncthreads();
    }
    if (i < n) off[i + 1] = sh[tid];
    if (tid == 1023) bsum[blockIdx.x] = sh[1023];
}
__global__ void k_scan_bsum3(int* __restrict__ bsum, int nb1, int nb2, int nb3) {
    __shared__ int sh[3][128];
    int seg = threadIdx.x >> 7;
    int t = threadIdx.x & 127;
    int base = (seg == 0) ? 0 : ((seg == 1) ? nb1 : nb1 + nb2);
    int nb = (seg == 0) ? nb1 : ((seg == 1) ? nb2 : nb3);
    int v = (t < nb) ? bsum[base + t] : 0;
    sh[seg][t] = v;
    __syncthreads();
    for (int d = 1; d < 128; d <<= 1) {
        int x = 0;
        if (t >= d) x = sh[seg][t - d];
        __syncthreads();
        if (t >= d) sh[seg][t] += x;
        __syncthreads();
    }
    if (t < nb) bsum[base + t] = sh[seg][t] - v;
}
__global__ void k_scan_add3(
    int n1, int* __restrict__ o1, int* __restrict__ c1, int nb1,
    int n2, int* __restrict__ o2, int* __restrict__ c2, int nb2,
    int n3, int* __restrict__ o3, int* __restrict__ c3,
    const int* __restrict__ bsum) {
    int b = blockIdx.x;
    int* off; int* cur; int n; int lb;
    if (b < nb1)            { off = o1; cur = c1; n = n1; lb = b; }
    else if (b < nb1 + nb2) { off = o2; cur = c2; n = n2; lb = b - nb1; }
    else                    { off = o3; cur = c3; n = n3; lb = b - nb1 - nb2; }
    int i = lb * 1024 + threadIdx.x;
    if (i < n) {
        int v = off[i + 1] + bsum[b];
        off[i + 1] = v;
        if (i + 1 < n) cur[i + 1] = v;
    }
    if (i == 0) { off[0] = 0; cur[0] = 0; }
}
__global__ void k_fill3(
    const int* __restrict__ s1, const int* __restrict__ d1, int E1,
    int* __restrict__ c1, int* __restrict__ e1,
    const int* __restrict__ s2, const int* __restrict__ d2, int E2,
    int* __restrict__ c2, int* __restrict__ e2,
    const int* __restrict__ s3, const int* __restrict__ d3, int E3,
    int* __restrict__ c3, int* __restrict__ e3) {
    int i = blockIdx.x * blockDim.x + threadIdx.x;
    if (i < E1) { int p = atomicAdd(&c1[d1[i]], 1); e1[p] = s1[i]; }
    else { i -= E1;
        if (i < E2) { int p = atomicAdd(&c2[d2[i]], 1); e2[p] = s2[i]; }
        else { i -= E2;
            if (i < E3) { int p = atomicAdd(&c3[d3[i]], 1); e3[p] = s3[i]; } } }
}

// ---------------- gather core (single accumulator — proven form) ----------------
__device__ __forceinline__ void gather_row(
    const uint2* __restrict__ x, const int* __restrict__ edges,
    const int* __restrict__ off, uint2* __restrict__ out,
    int d, int lane, int domean) {
    int beg = off[d], end = off[d + 1];
    float4 acc = make_float4(0.f, 0.f, 0.f, 0.f);
    for (int e = beg; e < end; e++) {
        int s = edges[e];
        uint2 u = __ldg(&x[(size_t)s * 32 + lane]);
        float2 f0 = __half22float2(*reinterpret_cast<__half2*>(&u.x));
        float2 f1 = __half22float2(*reinterpret_cast<__half2*>(&u.y));
        acc.x += f0.x; acc.y += f0.y; acc.z += f1.x; acc.w += f1.y;
    }
    if (domean) {
        int c = end - beg; if (c < 1) c = 1;
        float inv = 1.0f / (float)c;
        acc.x *= inv; acc.y *= inv; acc.z *= inv; acc.w *= inv;
    }
    uint2 o;
    o.x = pack_h2(acc.x, acc.y);
    o.y = pack_h2(acc.z, acc.w);
    out[(size_t)d * 32 + lane] = o;
}

// all 3 graphs (layer 0); block 0 zeroes colstats
__global__ void k_gather3(
    const uint2* __restrict__ xsrcS, const uint2* __restrict__ xsrcI,
    const int* __restrict__ eResp, const int* __restrict__ oResp,
    const int* __restrict__ eRev,  const int* __restrict__ oRev,
    const int* __restrict__ ePrec, const int* __restrict__ oPrec,
    uint2* __restrict__ aggI, uint2* __restrict__ aggS, uint2* __restrict__ aggP,
    int NI, int NS, float* __restrict__ colstats) {
    if (blockIdx.x == 0 && threadIdx.x < 256) colstats[threadIdx.x] = 0.f;
    int w = (blockIdx.x * blockDim.x + threadIdx.x) >> 5;
    int lane = threadIdx.x & 31;
    if (w < NI)               gather_row(xsrcS, eResp, oResp, aggI, w, lane, 1);
    else if (w < NI + NS)     gather_row(xsrcI, eRev,  oRev,  aggS, w - NI, lane, 1);
    else if (w < NI + 2 * NS) gather_row(xsrcS, ePrec, oPrec, aggP, w - NI - NS, lane, 0);
}

// rev->aggS only (reads xi16; layer 1, runs on s2 under the student GEMM)
__global__ void k_gatherS(
    const uint2* __restrict__ xsrcI,
    const int* __restrict__ eRev, const int* __restrict__ oRev,
    uint2* __restrict__ aggS, int NS) {
    int w = (blockIdx.x * blockDim.x + threadIdx.x) >> 5;
    int lane = threadIdx.x & 31;
    if (w < NS) gather_row(xsrcI, eRev, oRev, aggS, w, lane, 1);
}

// resp->aggI + prec->aggP (reads xs16; layer 1, main); block 0 zeroes colstats
__global__ void k_gatherIP(
    const uint2* __restrict__ xsrcS,
    const int* __restrict__ eResp, const int* __restrict__ oResp,
    const int* __restrict__ ePrec, const int* __restrict__ oPrec,
    uint2* __restrict__ aggI, uint2* __restrict__ aggP,
    int NI, int NS, float* __restrict__ colstats) {
    if (blockIdx.x == 0 && threadIdx.x < 256) colstats[threadIdx.x] = 0.f;
    int w = (blockIdx.x * blockDim.x + threadIdx.x) >> 5;
    int lane = threadIdx.x & 31;
    if (w < NI)           gather_row(xsrcS, eResp, oResp, aggI, w, lane, 1);
    else if (w < NI + NS) gather_row(xsrcS, ePrec, oPrec, aggP, w - NI, lane, 0);
}

// ---------------- FP16 tensor-core GEMM (C-write optional) ----------------
#define BK   32
#define LDW  20
#define TILEW (128 * LDW)

__device__ __forceinline__ void cp16(uint32_t dst, const void* src, int srcsize) {
    asm volatile("cp.async.cg.shared.global [%0], [%1], 16, %2;"
                 :: "r"(dst), "l"(src), "r"(srcsize));
}

__device__ __forceinline__ void mma_f16(float c[4],
                                        uint32_t a0, uint32_t a1, uint32_t a2, uint32_t a3,
                                        uint32_t b0, uint32_t b1) {
    asm volatile(
        "mma.sync.aligned.m16n8k16.row.col.f32.f16.f16.f32 "
        "{%0,%1,%2,%3}, {%4,%5,%6,%7}, {%8,%9}, {%0,%1,%2,%3};"
        : "+f"(c[0]), "+f"(c[1]), "+f"(c[2]), "+f"(c[3])
        : "r"(a0), "r"(a1), "r"(a2), "r"(a3), "r"(b0), "r"(b1));
}

__global__ __launch_bounds__(256, 2) void k_gemm_tc(
    const unsigned short* __restrict__ A0, const unsigned short* __restrict__ A1,
    const unsigned short* __restrict__ A2,
    const unsigned short* __restrict__ W0, const unsigned short* __restrict__ W1,
    const unsigned short* __restrict__ W2,
    const float* __restrict__ b0, const float* __restrict__ b1,
    float scale, int mode, int NA, int M,
    float* __restrict__ C, unsigned short* __restrict__ Cshadow,
    float* __restrict__ colsum, float* __restrict__ colsq) {

    extern __shared__ uint32_t smemu[];
    uint32_t* sA = smemu;
    uint32_t* sB = smemu + 4 * TILEW;
    __shared__ float ssum[128], ssq[128];

    const int tid  = threadIdx.x;
    const int m0   = blockIdx.x * 128;
    const int warp = tid >> 5;
    const int lane = tid & 31;
    const int wm   = warp >> 1;
    const int wn   = warp & 1;
    const int g    = lane >> 2;
    const int t4   = lane & 3;

    const int c0 = tid * 2;

    const unsigned short* Aarr[3] = {A0, A1, A2};
    const unsigned short* Warr[3] = {W0, W1, W2};

    const uint32_t sA_addr = (uint32_t)__cvta_generic_to_shared(sA);
    const uint32_t sB_addr = (uint32_t)__cvta_generic_to_shared(sB);

    float acc[2][8][4];
#pragma unroll
    for (int i = 0; i < 2; i++)
#pragma unroll
        for (int j = 0; j < 8; j++)
#pragma unroll
            for (int c = 0; c < 4; c++) acc[i][j][c] = 0.f;

    const int KT = NA * (D / BK);

    auto issue = [&](int t, int st) {
        int a  = t >> 2;
        int k0 = (t & 3) * BK;
        const unsigned short* A = Aarr[a];
        const unsigned short* W = Warr[a];
        uint32_t dA = sA_addr + st * (TILEW * 4);
        uint32_t dB = sB_addr + st * (TILEW * 4);
#pragma unroll
        for (int i = 0; i < 2; i++) {
            int c   = c0 + i;
            int row = c >> 2;
            int seg = c & 3;
            uint32_t doff = (uint32_t)(row * LDW + seg * 4) * 4;
            int szA = (m0 + row < M) ? 16 : 0;
            cp16(dA + doff, A + (size_t)(m0 + row) * D + k0 + seg * 8, szA);
            cp16(dB + doff, W + (size_t)row * D + k0 + seg * 8, 16);
        }
        asm volatile("cp.async.commit_group;");
    };

#pragma unroll
    for (int s = 0; s < 3; s++) issue(s, s);

    for (int t = 0; t < KT; t++) {
        asm volatile("cp.async.wait_group 2;");
        __syncthreads();

        if (t + 3 < KT) issue(t + 3, (t + 3) & 3);
        else asm volatile("cp.async.commit_group;");

        const uint32_t* cA = sA + (t & 3) * TILEW;
        const uint32_t* cB = sB + (t & 3) * TILEW;
#pragma unroll
        for (int kk2 = 0; kk2 < 2; kk2++) {
            const int wk = kk2 * 8;
            uint32_t af[2][4];
#pragma unroll
            for (int i = 0; i < 2; i++) {
                int mb = wm * 32 + i * 16;
                af[i][0] = cA[(mb + g)     * LDW + wk + t4];
                af[i][1] = cA[(mb + g + 8) * LDW + wk + t4];
                af[i][2] = cA[(mb + g)     * LDW + wk + t4 + 4];
                af[i][3] = cA[(mb + g + 8) * LDW + wk + t4 + 4];
            }
#pragma unroll
            for (int j = 0; j < 8; j++) {
                int nb = wn * 64 + j * 8;
                uint32_t bf0 = cB[(nb + g) * LDW + wk + t4];
                uint32_t bf1 = cB[(nb + g) * LDW + wk + t4 + 4];
                mma_f16(acc[0][j], af[0][0], af[0][1], af[0][2], af[0][3], bf0, bf1);
                mma_f16(acc[1][j], af[1][0], af[1][1], af[1][2], af[1][3], bf0, bf1);
            }
        }
        __syncthreads();
    }

    if (mode == 1) {
        if (tid < 128) { ssum[tid] = 0.f; ssq[tid] = 0.f; }
        __syncthreads();
    }

    float2 bias[8];
#pragma unroll
    for (int j = 0; j < 8; j++) {
        int col = wn * 64 + j * 8 + t4 * 2;
        bias[j].x = b0[col]     + (b1 ? b1[col]     : 0.f);
        bias[j].y = b0[col + 1] + (b1 ? b1[col + 1] : 0.f);
    }

    float ps[16], pq[16];
#pragma unroll
    for (int j = 0; j < 16; j++) { ps[j] = 0.f; pq[j] = 0.f; }

#pragma unroll
    for (int i = 0; i < 2; i++) {
        int row0 = m0 + wm * 32 + i * 16 + g;
        int row1 = row0 + 8;
#pragma unroll
        for (int j = 0; j < 8; j++) {
            int col = wn * 64 + j * 8 + t4 * 2;
            if (row0 < M) {
                float v0 = scale * (acc[i][j][0] + bias[j].x);
                float v1 = scale * (acc[i][j][1] + bias[j].y);
                if (mode == 1) {
                    v0 = (v0 > 0.f) ? v0 : expm1f(v0);
                    v1 = (v1 > 0.f) ? v1 : expm1f(v1);
                    ps[j * 2] += v0; pq[j * 2] += v0 * v0;
                    ps[j * 2 + 1] += v1; pq[j * 2 + 1] += v1 * v1;
                }
                if (C) *(float2*)(C + (size_t)row0 * D + col) = make_float2(v0, v1);
                if (Cshadow)
                    *(uint32_t*)(Cshadow + (size_t)row0 * D + col) = pack_h2(v0, v1);
            }
            if (row1 < M) {
                float v0 = scale * (acc[i][j][2] + bias[j].x);
                float v1 = scale * (acc[i][j][3] + bias[j].y);
                if (mode == 1) {
                    v0 = (v0 > 0.f) ? v0 : expm1f(v0);
                    v1 = (v1 > 0.f) ? v1 : expm1f(v1);
                    ps[j * 2] += v0; pq[j * 2] += v0 * v0;
                    ps[j * 2 + 1] += v1; pq[j * 2 + 1] += v1 * v1;
                }
                if (C) *(float2*)(C + (size_t)row1 * D + col) = make_float2(v0, v1);
                if (Cshadow)
                    *(uint32_t*)(Cshadow + (size_t)row1 * D + col) = pack_h2(v0, v1);
            }
        }
    }

    if (mode == 1) {
#pragma unroll
        for (int j = 0; j < 8; j++) {
            int col = wn * 64 + j * 8 + t4 * 2;
            atomicAdd(&ssum[col], ps[j * 2]);
            atomicAdd(&ssq[col], pq[j * 2]);
            atomicAdd(&ssum[col + 1], ps[j * 2 + 1]);
            atomicAdd(&ssq[col + 1], pq[j * 2 + 1]);
        }
        __syncthreads();
        if (tid < 128) {
            atomicAdd(&colsum[tid], ssum[tid]);
            atomicAdd(&colsq[tid], ssq[tid]);
        }
    }
}

// ---------------- batchnorm ----------------
__global__ void k_bn_prep(const float* __restrict__ stats, const float* __restrict__ g,
                          const float* __restrict__ b, float invN, float* __restrict__ ac) {
    int t = threadIdx.x;
    float m = stats[t] * invN;
    float var = stats[128 + t] * invN - m * m;
    float r = rsqrtf(var + 1e-5f);
    float a = g[t] * r;
    ac[t] = a;
    ac[128 + t] = b[t] - m * a;
}
__global__ void k_bn_apply(float4* __restrict__ x, int n4, const float* __restrict__ ac,
                           uint2* __restrict__ shadow) {
    __shared__ float sa[128], sc[128];
    if (threadIdx.x < 128) { sa[threadIdx.x] = ac[threadIdx.x]; sc[threadIdx.x] = ac[128 + threadIdx.x]; }
    __syncthreads();
    int stride = gridDim.x * blockDim.x;
    for (int i = blockIdx.x * blockDim.x + threadIdx.x; i < n4; i += stride) {
        float4 v = x[i];
        int c = (i & 31) * 4;
        v.x = v.x * sa[c + 0] + sc[c + 0];
        v.y = v.y * sa[c + 1] + sc[c + 1];
        v.z = v.z * sa[c + 2] + sc[c + 2];
        v.w = v.w * sa[c + 3] + sc[c + 3];
        x[i] = v;
        if (shadow) {
            uint2 u;
            u.x = pack_h2(v.x, v.y);
            u.y = pack_h2(v.z, v.w);
            shadow[i] = u;
        }
    }
}

// ---------------- host side ----------------
static void* sym_addr(const void* sym) {
    void* p = nullptr;
    cudaGetSymbolAddress(&p, sym);
    return p;
}

extern "C" void kernel_launch(void* const* d_in, const int* in_sizes, int n_in,
                              void* d_out, int out_size) {
    const float* x_student = (const float*)d_in[0];
    const float* x_item    = (const float*)d_in[1];
    const float* Wl_ri = (const float*)d_in[2];
    const float* bl_ri = (const float*)d_in[3];
    const float* Wr_ri = (const float*)d_in[4];
    const float* Wl_rs = (const float*)d_in[5];
    const float* bl_rs = (const float*)d_in[6];
    const float* Wr_rs = (const float*)d_in[7];
    const float* W_p   = (const float*)d_in[8];
    const float* b_p   = (const float*)d_in[9];
    const float* bn_g  = (const float*)d_in[10];
    const float* bn_b  = (const float*)d_in[11];
    const int* resp_src = (const int*)d_in[12];
    const int* resp_dst = (const int*)d_in[13];
    const int* rev_src  = (const int*)d_in[14];
    const int* rev_dst  = (const int*)d_in[15];
    const int* prec_src = (const int*)d_in[16];
    const int* prec_dst = (const int*)d_in[17];

    const int NS = in_sizes[0] / D;
    const int NI = in_sizes[1] / D;
    const int E1 = in_sizes[12];
    const int E2 = in_sizes[14];
    const int E3 = in_sizes[16];

    unsigned short* aggI = (unsigned short*)sym_addr(g_aggI);
    unsigned short* aggS = (unsigned short*)sym_addr(g_aggS);
    unsigned short* aggP = (unsigned short*)sym_addr(g_aggP);
    unsigned short* xs16 = (unsigned short*)sym_addr(g_xs16);
    unsigned short* xi16 = (unsigned short*)sym_addr(g_xi16);
    unsigned short* w_lri = (unsigned short*)sym_addr(g_w_lri);
    unsigned short* w_rri = (unsigned short*)sym_addr(g_w_rri);
    unsigned short* w_lrs = (unsigned short*)sym_addr(g_w_lrs);
    unsigned short* w_rrs = (unsigned short*)sym_addr(g_w_rrs);
    unsigned short* w_p   = (unsigned short*)sym_addr(g_w_p);
    int* off_resp  = (int*)sym_addr(g_off_resp);
    int* edge_resp = (int*)sym_addr(g_edge_resp);
    int* off_rev   = (int*)sym_addr(g_off_rev);
    int* edge_rev  = (int*)sym_addr(g_edge_rev);
    int* off_prec  = (int*)sym_addr(g_off_prec);
    int* edge_prec = (int*)sym_addr(g_edge_prec);
    int* cnt_resp  = (int*)sym_addr(g_cnt_resp);
    int* cnt_rev   = (int*)sym_addr(g_cnt_rev);
    int* cnt_prec  = (int*)sym_addr(g_cnt_prec);
    int* bsum      = (int*)sym_addr(g_bsum);
    float* colstats = (float*)sym_addr(g_colstats);
    float* bn_ac    = (float*)sym_addr(g_bn_ac);

    float* xi_out = (float*)d_out;                 // NI x D
    float* xs_out = xi_out + (size_t)NI * D;       // NS x D

    static int init_done = 0;
    static cudaStream_t s2;
    static cudaEvent_t ev_fork, ev_cvt, ev_g, ev_bn, ev_s, ev_ip, ev_j;
    const int SMEM_DYN = 8 * TILEW * 4;  // 81920 B
    if (!init_done) {
        cudaFuncSetAttribute(k_gemm_tc, cudaFuncAttributeMaxDynamicSharedMemorySize, SMEM_DYN);
        cudaStreamCreateWithFlags(&s2, cudaStreamNonBlocking);
        cudaEventCreateWithFlags(&ev_fork, cudaEventDisableTiming);
        cudaEventCreateWithFlags(&ev_cvt, cudaEventDisableTiming);
        cudaEventCreateWithFlags(&ev_g, cudaEventDisableTiming);
        cudaEventCreateWithFlags(&ev_bn, cudaEventDisableTiming);
        cudaEventCreateWithFlags(&ev_s, cudaEventDisableTiming);
        cudaEventCreateWithFlags(&ev_ip, cudaEventDisableTiming);
        cudaEventCreateWithFlags(&ev_j, cudaEventDisableTiming);
        init_done = 1;
    }

    // ---- fork: cvt_all on s2, concurrent with CSR build on main ----
    cudaEventRecord(ev_fork, 0);
    cudaStreamWaitEvent(s2, ev_fork, 0);
    {
        int n4s = NS * D / 4, n4i = NI * D / 4, n4w = 2 * D * D / 4;
        int tot = n4s + n4i + 5 * n4w;
        k_cvt_all<<<(tot + 255) / 256, 256, 0, s2>>>(
            (const float4*)x_student, (const float4*)x_item,
            (const float4*)Wl_ri, (const float4*)Wr_ri,
            (const float4*)Wl_rs, (const float4*)Wr_rs, (const float4*)W_p,
            (uint2*)xs16, (uint2*)xi16,
            (uint2*)w_lri, (uint2*)w_rri,
            (uint2*)w_lrs, (uint2*)w_rrs, (uint2*)w_p,
            n4s, n4i, n4w);
    }
    cudaEventRecord(ev_cvt, s2);

    // ---- fused CSR build (main stream) ----
    const int Etot = E1 + E2 + E3;
    const int Ntot = NI + NS + NS;
    const int nb1 = (NI + 1023) / 1024;
    const int nb2 = (NS + 1023) / 1024;
    const int nb3 = (NS + 1023) / 1024;
    k_zero3<<<(Ntot + 255) / 256, 256>>>(cnt_resp, NI, cnt_rev, NS, cnt_prec, NS);
    k_count3<<<(Etot + 255) / 256, 256>>>(resp_dst, E1, cnt_resp,
                                          rev_dst, E2, cnt_rev,
                                          prec_dst, E3, cnt_prec);
    k_scan_block3<<<nb1 + nb2 + nb3, 1024>>>(cnt_resp, NI, off_resp, nb1,
                                             cnt_rev, NS, off_rev, nb2,
                                             cnt_prec, NS, off_prec, bsum);
    k_scan_bsum3<<<1, 384>>>(bsum, nb1, nb2, nb3);
    k_scan_add3<<<nb1 + nb2 + nb3, 1024>>>(NI, off_resp, cnt_resp, nb1,
                                           NS, off_rev, cnt_rev, nb2,
                                           NS, off_prec, cnt_prec, bsum);
    k_fill3<<<(Etot + 255) / 256, 256>>>(resp_src, resp_dst, E1, cnt_resp, edge_resp,
                                         rev_src, rev_dst, E2, cnt_rev, edge_rev,
                                         prec_src, prec_dst, E3, cnt_prec, edge_prec);

    // join cvt before first gather
    cudaStreamWaitEvent(0, ev_cvt, 0);

    const int gBlocks3  = (NI + 2 * NS + 7) / 8;   // 8 warps per 256-thread block
    const int gBlocksS  = (NS + 7) / 8;
    const int gBlocksIP = (NI + NS + 7) / 8;
    const int gbI = (NI + 127) / 128;
    const int gbS = (NS + 127) / 128;
    const size_t wD = (size_t)D * D;

    // ================= layer 0 =================
    // fused gather (main); zeroes colstats
    k_gather3<<<gBlocks3, 256>>>(
        (const uint2*)xs16, (const uint2*)xi16,
        edge_resp, off_resp, edge_rev, off_rev, edge_prec, off_prec,
        (uint2*)aggI, (uint2*)aggS, (uint2*)aggP,
        NI, NS, colstats);
    cudaEventRecord(ev_g, 0);

    // branch A (s2): item path L0 -> xi_out + xi16 shadow
    cudaStreamWaitEvent(s2, ev_g, 0);
    k_gemm_tc<<<gbI, 256, SMEM_DYN, s2>>>(aggI, xi16, nullptr,
                                          w_lri, w_rri, nullptr,
                                          bl_ri, nullptr,
                                          1.0f, 1, 2, NI, xi_out, nullptr,
                                          colstats, colstats + 128);
    k_bn_prep<<<1, 128, 0, s2>>>(colstats, bn_g, bn_b, 1.0f / (float)NI, bn_ac);
    k_bn_apply<<<512, 256, 0, s2>>>((float4*)xi_out, NI * 32, bn_ac, (uint2*)xi16);
    cudaEventRecord(ev_bn, s2);

    // branch A continues (s2): layer-1 aggS gather (reads xi16) under the student GEMM
    k_gatherS<<<gBlocksS, 256, 0, s2>>>((const uint2*)xi16, edge_rev, off_rev,
                                        (uint2*)aggS, NS);
    cudaEventRecord(ev_s, s2);

    // branch B (main): student GEMM L0 -> xs16 shadow only (fp32 C is dead)
    k_gemm_tc<<<gbS, 256, SMEM_DYN>>>(aggS, xs16, aggP,
                                      w_lrs, w_rrs, w_p,
                                      bl_rs, b_p,
                                      0.5f, 0, 3, NS,
                                      nullptr, xs16,
                                      nullptr, nullptr);

    // ================= layer 1 =================
    // main: aggI + aggP gather (reads xs16); zeroes colstats — must wait until
    // bn_prep L0 has consumed the old colstats (ev_bn covers it)
    cudaStreamWaitEvent(0, ev_bn, 0);
    k_gatherIP<<<gBlocksIP, 256>>>((const uint2*)xs16,
                                   edge_resp, off_resp, edge_prec, off_prec,
                                   (uint2*)aggI, (uint2*)aggP,
                                   NI, NS, colstats);
    cudaEventRecord(ev_ip, 0);

    // branch A (s2): item path L1 (needs aggI + zeroed colstats from main)
    cudaStreamWaitEvent(s2, ev_ip, 0);
    k_gemm_tc<<<gbI, 256, SMEM_DYN, s2>>>(aggI, xi16, nullptr,
                                          w_lri + wD, w_rri + wD, nullptr,
                                          bl_ri + D, nullptr,
                                          1.0f, 1, 2, NI, xi_out, nullptr,
                                          colstats, colstats + 128);
    k_bn_prep<<<1, 128, 0, s2>>>(colstats, bn_g + D, bn_b + D, 1.0f / (float)NI, bn_ac);
    k_bn_apply<<<512, 256, 0, s2>>>((float4*)xi_out, NI * 32, bn_ac, nullptr);
    cudaEventRecord(ev_j, s2);

    // branch B (main): student GEMM L1 (needs aggS from s2, aggP from main)
    cudaStreamWaitEvent(0, ev_s, 0);
    k_gemm_tc<<<gbS, 256, SMEM_DYN>>>(aggS, xs16, aggP,
                                      w_lrs + wD, w_rrs + wD, w_p + wD,
                                      bl_rs + D, b_p + D,
                                      0.5f, 0, 3, NS,
                                      xs_out, nullptr,
                                      nullptr, nullptr);

    // join item branch before return
    cudaStreamWaitEvent(0, ev_j, 0);
}